// round 16
// baseline (speedup 1.0000x reference)
#include <cuda_runtime.h>
#include <cstdint>

// AccumulateLoss: CONTINLEN=5 pose-consistency loss.
// inputs: d_in[0] = rotas  (10, B, 3, 3) fp32
//         d_in[1] = transs (10, B, 3)    fp32
// output: d_out[0] = sum((R1@R2 - R12)^2)*50 + sum((R1@t1 + t2 - t12)^2)
//
// FINAL: warp-autonomous depth-2 cp.async pipelines, grid-strided tiles,
// 8 warps/SM. At 96-98% of delivered HBM bandwidth for this access pattern
// (5.0 TB/s measured; 126 MB floor = 25.1us vs 25.6-26.3us kernel). Pipeline
// depth 1/3/4, TMA path, 4-16 warps/SM, blocked ranges, and L2 prefetch
// hints all measured equal or worse (rounds 5-13); same-binary variance
// band is 26.8-27.4us.

#define NPAIRS 10
#define BETA   50.0f
#define WTILE  32                    // batch elements per warp-tile
#define WARPS_PER_CTA 2
#define BLOCK_T (WARPS_PER_CTA * 32) // 64 threads
#define NBLOCKS 592                  // 148 SMs x 4 CTAs (smem: 46KB/CTA)
#define WSLAB_F (WTILE * 9)          // 288 floats per pair per warp-tile
#define WSTAGE_F (NPAIRS * WSLAB_F)  // 2880 floats = 11520 B per stage

// triples (i,k,j) flattened to pair ids: (p1, p2, p12) — literal constants.
#define FOR_EACH_TRIPLE(X) \
    X(0,4,1) X(0,5,2) X(0,6,3) X(1,7,2) X(1,8,3) \
    X(2,9,3) X(4,7,5) X(4,8,6) X(5,9,6) X(7,9,8)

__device__ double g_acc;              // zero-init; reset by last block each launch
__device__ unsigned int g_counter;    // zero-init; reset by last block each launch

__device__ __forceinline__ uint32_t smem_u32(const void* p) {
    return (uint32_t)__cvta_generic_to_shared(p);
}
__device__ __forceinline__ void cp_async16(uint32_t s, const void* g) {
    asm volatile("cp.async.cg.shared.global [%0], [%1], 16;\n" :: "r"(s), "l"(g));
}
__device__ __forceinline__ void cp_async4(uint32_t s, const void* g) {
    asm volatile("cp.async.ca.shared.global [%0], [%1], 4;\n" :: "r"(s), "l"(g));
}
__device__ __forceinline__ void cp_commit() {
    asm volatile("cp.async.commit_group;\n" ::: "memory");
}
__device__ __forceinline__ void cp_wait1() {
    asm volatile("cp.async.wait_group 1;\n" ::: "memory");
}

__global__ __launch_bounds__(BLOCK_T)
void accum_loss_kernel(const float* __restrict__ rotas,
                       const float* __restrict__ transs,
                       float* __restrict__ out,
                       int B, int nwt, int totalwarps) {
    // per-warp private double-buffered R slabs: [warp][buf][2880 floats]
    __shared__ float sR[WARPS_PER_CTA][2][WSTAGE_F];   // 46080 B

    const int lane = threadIdx.x & 31;
    const int wid  = threadIdx.x >> 5;
    const int gwarp = blockIdx.x * WARPS_PER_CTA + wid;

    const size_t PB9 = (size_t)B * 9;
    const size_t PB3 = (size_t)B * 3;

    // ---- cp.async stage of this warp-tile's R into stage `buf` ----
    auto prefetch = [&](int wt, int buf) {
        const int b0 = wt * WTILE;
        const int nvalid = min(WTILE, B - b0);
        float* st = sR[wid][buf];
        if (nvalid == WTILE) {
            #pragma unroll
            for (int p = 0; p < NPAIRS; p++) {
                const float4* g = (const float4*)(rotas + (size_t)p * PB9 + (size_t)b0 * 9);
                uint32_t s = smem_u32(st + p * WSLAB_F);
                #pragma unroll
                for (int i = 0; i < 3; i++) {            // 72 float4 per pair
                    int idx = i * 32 + lane;
                    if (idx < WSLAB_F / 4)
                        cp_async16(s + idx * 16, g + idx);
                }
            }
        } else {
            for (int p = 0; p < NPAIRS; p++) {
                const float* g = rotas + (size_t)p * PB9 + (size_t)b0 * 9;
                uint32_t s = smem_u32(st + p * WSLAB_F);
                for (int i = lane; i < nvalid * 9; i += 32)
                    cp_async4(s + i * 4, g + i);
            }
        }
    };

    float loss = 0.0f;

    int wt = gwarp;
    int buf = 0;
    if (wt < nwt) prefetch(wt, 0);
    cp_commit();

    for (; wt < nwt; wt += totalwarps) {
        const int b0 = wt * WTILE;
        const int nvalid = min(WTILE, B - b0);

        // t: direct per-thread LDG (warp covers 384 dense bytes/pair) —
        // issued before the wait so its latency overlaps the pipeline wait.
        float t[NPAIRS][3];
        if (lane < nvalid) {
            const int b = b0 + lane;
            #pragma unroll
            for (int p = 0; p < NPAIRS; p++) {
                const float* src = transs + (size_t)p * PB3 + (size_t)b * 3;
                t[p][0] = src[0]; t[p][1] = src[1]; t[p][2] = src[2];
            }
        }

        // issue next tile's loads before waiting on the current tile
        const int nxt = wt + totalwarps;
        if (nxt < nwt) prefetch(nxt, buf ^ 1);
        cp_commit();            // exactly one group per iteration

        cp_wait1();             // all but the newest group complete
        __syncwarp();           // all lanes' groups done before any lane reads

        if (lane < nvalid) {
            const float* st = sR[wid][buf];
            // 90 conflict-free LDS (stride 9, gcd(9,32)=1)
            float r[NPAIRS][9];
            const float* myR = st + lane * 9;
            #pragma unroll
            for (int p = 0; p < NPAIRS; p++) {
                #pragma unroll
                for (int e = 0; e < 9; e++)
                    r[p][e] = myR[p * WSLAB_F + e];
            }

            float ra = 0.0f, ta = 0.0f;

            #define DO_TRIPLE(p1, p2, p12)                                     \
            {                                                                  \
                _Pragma("unroll")                                              \
                for (int i = 0; i < 3; i++) {                                  \
                    _Pragma("unroll")                                          \
                    for (int j = 0; j < 3; j++) {                              \
                        float s = fmaf(r[p1][i*3+0], r[p2][0*3+j],             \
                                  fmaf(r[p1][i*3+1], r[p2][1*3+j],             \
                                       r[p1][i*3+2] * r[p2][2*3+j]));          \
                        float d = s - r[p12][i*3+j];                           \
                        ra = fmaf(d, d, ra);                                   \
                    }                                                          \
                }                                                              \
                _Pragma("unroll")                                              \
                for (int i = 0; i < 3; i++) {                                  \
                    float s = fmaf(r[p1][i*3+0], t[p1][0],                     \
                              fmaf(r[p1][i*3+1], t[p1][1],                     \
                              fmaf(r[p1][i*3+2], t[p1][2], t[p2][i])));        \
                    float d = s - t[p12][i];                                   \
                    ta = fmaf(d, d, ta);                                       \
                }                                                              \
            }

            FOR_EACH_TRIPLE(DO_TRIPLE)
            #undef DO_TRIPLE

            loss += fmaf(ra, BETA, ta);
        }

        __syncwarp();           // lanes done reading sR[wid][buf] before refill
        buf ^= 1;
    }

    // ---- Reduction: warp -> CTA -> global ----
    #pragma unroll
    for (int off = 16; off > 0; off >>= 1)
        loss += __shfl_down_sync(0xffffffffu, loss, off);

    __shared__ double warp_sums[WARPS_PER_CTA];
    __shared__ bool is_last;
    if (lane == 0) warp_sums[wid] = (double)loss;
    __syncthreads();

    if (threadIdx.x == 0) {
        double s = 0.0;
        #pragma unroll
        for (int w = 0; w < WARPS_PER_CTA; w++) s += warp_sums[w];
        atomicAdd(&g_acc, s);
        __threadfence();
        unsigned int done = atomicAdd(&g_counter, 1u);
        is_last = (done == gridDim.x - 1u);
    }
    __syncthreads();

    // ---- Last block writes result and resets state for the next graph replay ----
    if (is_last && threadIdx.x == 0) {
        unsigned long long old = atomicExch((unsigned long long*)&g_acc, 0ull);
        out[0] = (float)__longlong_as_double((long long)old);
        __threadfence();
        g_counter = 0u;
    }
}

extern "C" void kernel_launch(void* const* d_in, const int* in_sizes, int n_in,
                              void* d_out, int out_size) {
    const float* rotas  = (const float*)d_in[0];
    const float* transs = (const float*)d_in[1];
    float* out = (float*)d_out;

    const int B = in_sizes[0] / (NPAIRS * 9);
    const int nwt = (B + WTILE - 1) / WTILE;          // warp-tiles (8192)
    int nblocks = NBLOCKS;
    if (nblocks * WARPS_PER_CTA > nwt)
        nblocks = (nwt + WARPS_PER_CTA - 1) / WARPS_PER_CTA;
    const int totalwarps = nblocks * WARPS_PER_CTA;

    accum_loss_kernel<<<nblocks, BLOCK_T>>>(rotas, transs, out, B, nwt, totalwarps);
}

// round 17
// speedup vs baseline: 1.2107x; 1.2107x over previous
#include <cuda_runtime.h>
#include <cstdint>

// AccumulateLoss: CONTINLEN=5 pose-consistency loss.
// inputs: d_in[0] = rotas  (10, B, 3, 3) fp32   (94.4 MB — streaming, evict_first)
//         d_in[1] = transs (10, B, 3)    fp32   (31.5 MB — pinned, evict_last)
// output: d_out[0] = sum((R1@R2 - R12)^2)*50 + sum((R1@t1 + t2 - t12)^2)
//
// R7 optimum (warp-autonomous depth-2 cp.async pipelines, 8 warps/SM) +
// L2 residency partitioning: the 125.8 MB working set exactly thrashes the
// ~126 MB L2 across graph replays (measured: full 130 MB from DRAM each
// launch). Pinning transs with evict_last and streaming rotas with
// evict_first keeps transs L2-resident across replays, cutting DRAM
// traffic by ~25%.

#define NPAIRS 10
#define BETA   50.0f
#define WTILE  32                    // batch elements per warp-tile
#define WARPS_PER_CTA 2
#define BLOCK_T (WARPS_PER_CTA * 32) // 64 threads
#define NBLOCKS 592                  // 148 SMs x 4 CTAs (smem: 46KB/CTA)
#define WSLAB_F (WTILE * 9)          // 288 floats per pair per warp-tile
#define WSTAGE_F (NPAIRS * WSLAB_F)  // 2880 floats = 11520 B per stage

// triples (i,k,j) flattened to pair ids: (p1, p2, p12) — literal constants.
#define FOR_EACH_TRIPLE(X) \
    X(0,4,1) X(0,5,2) X(0,6,3) X(1,7,2) X(1,8,3) \
    X(2,9,3) X(4,7,5) X(4,8,6) X(5,9,6) X(7,9,8)

__device__ double g_acc;              // zero-init; reset by last block each launch
__device__ unsigned int g_counter;    // zero-init; reset by last block each launch

__device__ __forceinline__ uint32_t smem_u32(const void* p) {
    return (uint32_t)__cvta_generic_to_shared(p);
}
// cp.async 16B with L2 cache policy (evict_first for streaming R)
__device__ __forceinline__ void cp_async16_pol(uint32_t s, const void* g, uint64_t pol) {
    asm volatile("cp.async.cg.shared.global.L2::cache_hint [%0], [%1], 16, %2;\n"
                 :: "r"(s), "l"(g), "l"(pol));
}
__device__ __forceinline__ void cp_async4(uint32_t s, const void* g) {
    asm volatile("cp.async.ca.shared.global [%0], [%1], 4;\n" :: "r"(s), "l"(g));
}
__device__ __forceinline__ void cp_commit() {
    asm volatile("cp.async.commit_group;\n" ::: "memory");
}
__device__ __forceinline__ void cp_wait1() {
    asm volatile("cp.async.wait_group 1;\n" ::: "memory");
}
// ld.global with L2 cache policy (evict_last for pinned transs)
__device__ __forceinline__ float ldg_pol(const float* p, uint64_t pol) {
    float v;
    asm("ld.global.L2::cache_hint.f32 %0, [%1], %2;"
        : "=f"(v) : "l"(p), "l"(pol));
    return v;
}

__global__ __launch_bounds__(BLOCK_T)
void accum_loss_kernel(const float* __restrict__ rotas,
                       const float* __restrict__ transs,
                       float* __restrict__ out,
                       int B, int nwt, int totalwarps) {
    // per-warp private double-buffered R slabs: [warp][buf][2880 floats]
    __shared__ float sR[WARPS_PER_CTA][2][WSTAGE_F];   // 46080 B

    const int lane = threadIdx.x & 31;
    const int wid  = threadIdx.x >> 5;
    const int gwarp = blockIdx.x * WARPS_PER_CTA + wid;

    const size_t PB9 = (size_t)B * 9;
    const size_t PB3 = (size_t)B * 3;

    // L2 cache policies: rotas streams (evict_first), transs pins (evict_last)
    uint64_t pol_first, pol_last;
    asm("createpolicy.fractional.L2::evict_first.b64 %0, 1.0;" : "=l"(pol_first));
    asm("createpolicy.fractional.L2::evict_last.b64 %0, 1.0;"  : "=l"(pol_last));

    // ---- cp.async stage of this warp-tile's R into stage `buf` ----
    auto prefetch = [&](int wt, int buf) {
        const int b0 = wt * WTILE;
        const int nvalid = min(WTILE, B - b0);
        float* st = sR[wid][buf];
        if (nvalid == WTILE) {
            #pragma unroll
            for (int p = 0; p < NPAIRS; p++) {
                const float4* g = (const float4*)(rotas + (size_t)p * PB9 + (size_t)b0 * 9);
                uint32_t s = smem_u32(st + p * WSLAB_F);
                #pragma unroll
                for (int i = 0; i < 3; i++) {            // 72 float4 per pair
                    int idx = i * 32 + lane;
                    if (idx < WSLAB_F / 4)
                        cp_async16_pol(s + idx * 16, g + idx, pol_first);
                }
            }
        } else {
            for (int p = 0; p < NPAIRS; p++) {
                const float* g = rotas + (size_t)p * PB9 + (size_t)b0 * 9;
                uint32_t s = smem_u32(st + p * WSLAB_F);
                for (int i = lane; i < nvalid * 9; i += 32)
                    cp_async4(s + i * 4, g + i);
            }
        }
    };

    float loss = 0.0f;

    int wt = gwarp;
    int buf = 0;
    if (wt < nwt) prefetch(wt, 0);
    cp_commit();

    for (; wt < nwt; wt += totalwarps) {
        const int b0 = wt * WTILE;
        const int nvalid = min(WTILE, B - b0);

        // t: direct per-thread LDG with evict_last (pins transs in L2 across
        // graph replays) — issued before the wait to overlap the pipeline wait.
        float t[NPAIRS][3];
        if (lane < nvalid) {
            const int b = b0 + lane;
            #pragma unroll
            for (int p = 0; p < NPAIRS; p++) {
                const float* src = transs + (size_t)p * PB3 + (size_t)b * 3;
                t[p][0] = ldg_pol(src + 0, pol_last);
                t[p][1] = ldg_pol(src + 1, pol_last);
                t[p][2] = ldg_pol(src + 2, pol_last);
            }
        }

        // issue next tile's loads before waiting on the current tile
        const int nxt = wt + totalwarps;
        if (nxt < nwt) prefetch(nxt, buf ^ 1);
        cp_commit();            // exactly one group per iteration

        cp_wait1();             // all but the newest group complete
        __syncwarp();           // all lanes' groups done before any lane reads

        if (lane < nvalid) {
            const float* st = sR[wid][buf];
            // 90 conflict-free LDS (stride 9, gcd(9,32)=1)
            float r[NPAIRS][9];
            const float* myR = st + lane * 9;
            #pragma unroll
            for (int p = 0; p < NPAIRS; p++) {
                #pragma unroll
                for (int e = 0; e < 9; e++)
                    r[p][e] = myR[p * WSLAB_F + e];
            }

            float ra = 0.0f, ta = 0.0f;

            #define DO_TRIPLE(p1, p2, p12)                                     \
            {                                                                  \
                _Pragma("unroll")                                              \
                for (int i = 0; i < 3; i++) {                                  \
                    _Pragma("unroll")                                          \
                    for (int j = 0; j < 3; j++) {                              \
                        float s = fmaf(r[p1][i*3+0], r[p2][0*3+j],             \
                                  fmaf(r[p1][i*3+1], r[p2][1*3+j],             \
                                       r[p1][i*3+2] * r[p2][2*3+j]));          \
                        float d = s - r[p12][i*3+j];                           \
                        ra = fmaf(d, d, ra);                                   \
                    }                                                          \
                }                                                              \
                _Pragma("unroll")                                              \
                for (int i = 0; i < 3; i++) {                                  \
                    float s = fmaf(r[p1][i*3+0], t[p1][0],                     \
                              fmaf(r[p1][i*3+1], t[p1][1],                     \
                              fmaf(r[p1][i*3+2], t[p1][2], t[p2][i])));        \
                    float d = s - t[p12][i];                                   \
                    ta = fmaf(d, d, ta);                                       \
                }                                                              \
            }

            FOR_EACH_TRIPLE(DO_TRIPLE)
            #undef DO_TRIPLE

            loss += fmaf(ra, BETA, ta);
        }

        __syncwarp();           // lanes done reading sR[wid][buf] before refill
        buf ^= 1;
    }

    // ---- Reduction: warp -> CTA -> global ----
    #pragma unroll
    for (int off = 16; off > 0; off >>= 1)
        loss += __shfl_down_sync(0xffffffffu, loss, off);

    __shared__ double warp_sums[WARPS_PER_CTA];
    __shared__ bool is_last;
    if (lane == 0) warp_sums[wid] = (double)loss;
    __syncthreads();

    if (threadIdx.x == 0) {
        double s = 0.0;
        #pragma unroll
        for (int w = 0; w < WARPS_PER_CTA; w++) s += warp_sums[w];
        atomicAdd(&g_acc, s);
        __threadfence();
        unsigned int done = atomicAdd(&g_counter, 1u);
        is_last = (done == gridDim.x - 1u);
    }
    __syncthreads();

    // ---- Last block writes result and resets state for the next graph replay ----
    if (is_last && threadIdx.x == 0) {
        unsigned long long old = atomicExch((unsigned long long*)&g_acc, 0ull);
        out[0] = (float)__longlong_as_double((long long)old);
        __threadfence();
        g_counter = 0u;
    }
}

extern "C" void kernel_launch(void* const* d_in, const int* in_sizes, int n_in,
                              void* d_out, int out_size) {
    const float* rotas  = (const float*)d_in[0];
    const float* transs = (const float*)d_in[1];
    float* out = (float*)d_out;

    const int B = in_sizes[0] / (NPAIRS * 9);
    const int nwt = (B + WTILE - 1) / WTILE;          // warp-tiles (8192)
    int nblocks = NBLOCKS;
    if (nblocks * WARPS_PER_CTA > nwt)
        nblocks = (nwt + WARPS_PER_CTA - 1) / WARPS_PER_CTA;
    const int totalwarps = nblocks * WARPS_PER_CTA;

    accum_loss_kernel<<<nblocks, BLOCK_T>>>(rotas, transs, out, B, nwt, totalwarps);
}